// round 15
// baseline (speedup 1.0000x reference)
#include <cuda_runtime.h>
#include <cuda_fp16.h>
#include <cstdint>

// SwinStyleAttention. R14: fp16 SINGLE-PASS mma (fp16 has 11 mantissa bits;
// error budget 1e-3 permits it). MMAs /3, operand bytes /2 vs R12's bf16 3-pass.
// Weights as pre-packed ldmatrix-order fragments via LDG (no smem). 2 CTAs/SM.

#define SCALE_ 0.17677669529663687f
#define SWZ(row, colb) (((row) << 8) + ((colb) ^ (((row) & 7) << 4)))

#define XH    0            // x plane (64 rows x 128 fp16) -> V plane after v-gemm
#define KHP   16384
#define OHP   32768
#define BIASO 49152
#define SMEM_BYTES 49664

// Pre-packed B fragments in ldmatrix order (fp16, single precision level):
// index = (((c*4 + wn)*8 + kt)*32 + lane)*8 + j,  c: 0=q,1=k,2=v,3=proj
__device__ uint32_t g_bfrag[4 * 4 * 8 * 32 * 8];

static __device__ __forceinline__ uint32_t smem_u32(const void* p) {
    uint32_t a;
    asm("{ .reg .u64 t; cvta.to.shared.u64 t, %1; cvt.u32.u64 %0, t; }" : "=r"(a) : "l"(p));
    return a;
}
static __device__ __forceinline__ uint32_t pack2(float x, float y) {
    __half2 h = __floats2half2_rn(x, y);
    return *(uint32_t*)&h;
}

#define LDSM4(R0, R1, R2, R3, ADDR) \
    asm volatile("ldmatrix.sync.aligned.m8n8.x4.shared.b16 {%0,%1,%2,%3}, [%4];" \
                 : "=r"(R0), "=r"(R1), "=r"(R2), "=r"(R3) : "r"(ADDR))
#define LDSM4T(R0, R1, R2, R3, ADDR) \
    asm volatile("ldmatrix.sync.aligned.m8n8.x4.trans.shared.b16 {%0,%1,%2,%3}, [%4];" \
                 : "=r"(R0), "=r"(R1), "=r"(R2), "=r"(R3) : "r"(ADDR))
#define MMA(D, A, B) \
    asm volatile("mma.sync.aligned.m16n8k16.row.col.f32.f16.f16.f32 " \
                 "{%0,%1,%2,%3},{%4,%5,%6,%7},{%8,%9},{%0,%1,%2,%3};" \
                 : "+f"((D)[0]), "+f"((D)[1]), "+f"((D)[2]), "+f"((D)[3]) \
                 : "r"((A)[0]), "r"((A)[1]), "r"((A)[2]), "r"((A)[3]), \
                   "r"((B)[0]), "r"((B)[1]))

// ---- prep: pack W fragments exactly as ldmatrix would deliver them (fp16) ----
__global__ void prep_weights(const float* __restrict__ wqkv, const float* __restrict__ wproj) {
    int i = blockIdx.x * blockDim.x + threadIdx.x;      // 32768 entries
    if (i >= 32768) return;
    int j    = i & 7;
    int lane = (i >> 3) & 31;
    int kt   = (i >> 8) & 7;
    int wn   = (i >> 11) & 3;
    int c    = i >> 13;                                  // 0=q,1=k,2=v,3=proj
    int ng = j >> 2, m = j & 3;
    int p = 8 * m + (lane >> 2);
    int n = wn * 32 + ng * 16 + ((p >> 4) << 3) + (p & 7);
    int kbyte = kt * 32 + ((p >> 3) & 1) * 16 + 4 * (lane & 3);
    int k0 = kbyte >> 1;
    float v0, v1;
    if (c < 3) { v0 = wqkv[k0 * 384 + c * 128 + n]; v1 = wqkv[(k0 + 1) * 384 + c * 128 + n]; }
    else       { v0 = wproj[k0 * 128 + n];          v1 = wproj[(k0 + 1) * 128 + n]; }
    g_bfrag[i] = pack2(v0, v1);
}

// ---------------- main fused kernel: 2 CTAs/SM ----------------
__global__ __launch_bounds__(256, 2)
void swin_mma9_kernel(const float* __restrict__ x,
                      const float* __restrict__ b_proj,
                      float* __restrict__ out)
{
    extern __shared__ __align__(256) unsigned char smem[];
    const uint32_t sb = smem_u32(smem);

    const int tid = threadIdx.x;
    const int lane = tid & 31;
    const int warp = tid >> 5;     // 0..7
    const int g = lane >> 2;
    const int t4 = lane & 3;

    const int win = blockIdx.x;
    const int b = win >> 10, wy = (win >> 5) & 31, wx = win & 31;
    const int hbase = wy * 8 + 4, wbase = wx * 8 + 4;

    // ---- phase 0: bias + rolled-window gather into X plane (fp16) ----
    if (tid < 128) ((float*)(smem + BIASO))[tid] = b_proj[tid];
    #pragma unroll
    for (int it = 0; it < 4; it++) {
        int idx = tid + it * 256;
        int t = idx & 63, cq = idx >> 6;
        int h = (hbase + (t >> 3)) & 255;
        int w = (wbase + (t & 7)) & 255;
        const float* xg = x + (size_t)(b * 128 + cq * 8) * 65536 + h * 256 + w;
        uint32_t hp[4];
        #pragma unroll
        for (int jj = 0; jj < 4; jj++) {
            float f0 = xg[(size_t)(2 * jj) << 16];
            float f1 = xg[(size_t)(2 * jj + 1) << 16];
            hp[jj] = pack2(f0, f1);
        }
        *(uint4*)(smem + XH + SWZ(t, cq * 16)) = make_uint4(hp[0], hp[1], hp[2], hp[3]);
    }
    __syncthreads();               // S1: X visible

    const int mbase = (warp >> 2) * 32;
    const int nbase = (warp & 3) * 32;
    const int wn = warp & 3;

    float acc[2][4][4];
    // single-pass GEMM: A = smem plane, B = global pre-packed fragments (chunk c)
    auto gemm = [&](uint32_t aPl, int c) {
        #pragma unroll
        for (int mf = 0; mf < 2; mf++)
            #pragma unroll
            for (int nt = 0; nt < 4; nt++)
                #pragma unroll
                for (int q = 0; q < 4; q++) acc[mf][nt][q] = 0.f;
        const int arow = mbase + (lane & 15);
        const uint4* bp = (const uint4*)g_bfrag + (size_t)((c * 4 + wn) * 8) * 64 + lane * 2;
        uint32_t bfr[2][4][2];
        auto loadB = [&](int kt, int st) {
            uint4 h0 = bp[kt * 64], h1 = bp[kt * 64 + 1];
            bfr[st][0][0] = h0.x; bfr[st][0][1] = h0.y; bfr[st][1][0] = h0.z; bfr[st][1][1] = h0.w;
            bfr[st][2][0] = h1.x; bfr[st][2][1] = h1.y; bfr[st][3][0] = h1.z; bfr[st][3][1] = h1.w;
        };
        loadB(0, 0);
        #pragma unroll
        for (int kt = 0; kt < 8; kt++) {
            const int cur = kt & 1;
            if (kt < 7) loadB(kt + 1, cur ^ 1);
            uint32_t ah[2][4];
            const int acolb = kt * 32 + (lane >> 4) * 16;
            #pragma unroll
            for (int mf = 0; mf < 2; mf++)
                LDSM4(ah[mf][0], ah[mf][1], ah[mf][2], ah[mf][3],
                      sb + aPl + SWZ(arow + mf * 16, acolb));
            #pragma unroll
            for (int mf = 0; mf < 2; mf++)
                #pragma unroll
                for (int nt = 0; nt < 4; nt++)
                    MMA(acc[mf][nt], ah[mf], bfr[cur][nt]);
        }
    };
    auto store_y = [&](uint32_t yPl) {
        #pragma unroll
        for (int mf = 0; mf < 2; mf++)
            #pragma unroll
            for (int nt = 0; nt < 4; nt++) {
                int ch = nbase + nt * 8 + 2 * t4;
                int tok = mbase + mf * 16 + g;
                *(uint32_t*)(smem + yPl + SWZ(tok, ch * 2)) =
                    pack2(acc[mf][nt][0], acc[mf][nt][1]);
                *(uint32_t*)(smem + yPl + SWZ(tok + 8, ch * 2)) =
                    pack2(acc[mf][nt][2], acc[mf][nt][3]);
            }
    };

    // ---- k-gemm first (store early), then q-gemm (regs), then v-gemm ----
    gemm(XH, 1);
    store_y(KHP);

    gemm(XH, 0);
    uint32_t qf[2][2][4];          // [mf][kt16][frag], SCALE folded
    #pragma unroll
    for (int mf = 0; mf < 2; mf++)
        #pragma unroll
        for (int kt = 0; kt < 2; kt++) {
            qf[mf][kt][0] = pack2(acc[mf][2*kt][0] * SCALE_,   acc[mf][2*kt][1] * SCALE_);
            qf[mf][kt][1] = pack2(acc[mf][2*kt][2] * SCALE_,   acc[mf][2*kt][3] * SCALE_);
            qf[mf][kt][2] = pack2(acc[mf][2*kt+1][0] * SCALE_, acc[mf][2*kt+1][1] * SCALE_);
            qf[mf][kt][3] = pack2(acc[mf][2*kt+1][2] * SCALE_, acc[mf][2*kt+1][3] * SCALE_);
        }

    gemm(XH, 2);
    __syncthreads();               // S2: all X reads done; K visible
    store_y(XH);                   // V overwrites X plane
    __syncthreads();               // S3: V visible

    // ---- attention, per-mf; O -> O plane ----
    {
        const int chB = (warp & 3) * 64;
        #pragma unroll
        for (int mf = 0; mf < 2; mf++) {
            float s[8][4];
            #pragma unroll
            for (int j = 0; j < 8; j++)
                #pragma unroll
                for (int q = 0; q < 4; q++) s[j][q] = 0.f;

            {   // QK^T pipelined over smem K
                uint32_t kh[2][4];
                auto loadK = [&](int it, int st) {
                    const int kt = it >> 2, ng = it & 3;
                    const int bcolb = chB + kt * 32 + ((lane >> 3) & 1) * 16;
                    const int brow = ng * 16 + ((lane >> 4) << 3) + (lane & 7);
                    LDSM4(kh[st][0], kh[st][1], kh[st][2], kh[st][3], sb + KHP + SWZ(brow, bcolb));
                };
                loadK(0, 0);
                #pragma unroll
                for (int it = 0; it < 8; it++) {
                    const int cur = it & 1;
                    if (it < 7) loadK(it + 1, cur ^ 1);
                    const int kt = it >> 2, ng = it & 3;
                    MMA(s[2*ng],   qf[mf][kt], kh[cur]);
                    MMA(s[2*ng+1], qf[mf][kt], kh[cur] + 2);
                }
            }
            // softmax (scale already folded into q)
            float mx0 = -1e30f, mx1 = -1e30f;
            #pragma unroll
            for (int j = 0; j < 8; j++) {
                mx0 = fmaxf(mx0, fmaxf(s[j][0], s[j][1]));
                mx1 = fmaxf(mx1, fmaxf(s[j][2], s[j][3]));
            }
            mx0 = fmaxf(mx0, __shfl_xor_sync(0xffffffffu, mx0, 1));
            mx0 = fmaxf(mx0, __shfl_xor_sync(0xffffffffu, mx0, 2));
            mx1 = fmaxf(mx1, __shfl_xor_sync(0xffffffffu, mx1, 1));
            mx1 = fmaxf(mx1, __shfl_xor_sync(0xffffffffu, mx1, 2));
            float sm0 = 0.f, sm1 = 0.f;
            #pragma unroll
            for (int j = 0; j < 8; j++) {
                s[j][0] = __expf(s[j][0] - mx0); sm0 += s[j][0];
                s[j][1] = __expf(s[j][1] - mx0); sm0 += s[j][1];
                s[j][2] = __expf(s[j][2] - mx1); sm1 += s[j][2];
                s[j][3] = __expf(s[j][3] - mx1); sm1 += s[j][3];
            }
            sm0 += __shfl_xor_sync(0xffffffffu, sm0, 1);
            sm0 += __shfl_xor_sync(0xffffffffu, sm0, 2);
            sm1 += __shfl_xor_sync(0xffffffffu, sm1, 1);
            sm1 += __shfl_xor_sync(0xffffffffu, sm1, 2);
            const float inv0 = 1.f / sm0, inv1 = 1.f / sm1;

            // P @ V (V lives in X plane)
            float o[4][4];
            #pragma unroll
            for (int nt = 0; nt < 4; nt++)
                #pragma unroll
                for (int q = 0; q < 4; q++) o[nt][q] = 0.f;
            {
                uint32_t vf[2][4][2];
                auto loadV = [&](int kt, int st) {
                    const int vrow = kt * 16 + (lane & 15);
                    #pragma unroll
                    for (int ng = 0; ng < 2; ng++) {
                        const int vcolb = chB + ng * 32 + (lane >> 4) * 16;
                        uint32_t r0, r1, r2, r3;
                        LDSM4T(r0, r1, r2, r3, sb + XH + SWZ(vrow, vcolb));
                        vf[st][2 * ng][0] = r0; vf[st][2 * ng][1] = r1;
                        vf[st][2 * ng + 1][0] = r2; vf[st][2 * ng + 1][1] = r3;
                    }
                };
                loadV(0, 0);
                #pragma unroll
                for (int kt = 0; kt < 4; kt++) {
                    const int cur = kt & 1;
                    if (kt < 3) loadV(kt + 1, cur ^ 1);
                    uint32_t pa[4];
                    pa[0] = pack2(s[2*kt][0] * inv0,   s[2*kt][1] * inv0);
                    pa[1] = pack2(s[2*kt][2] * inv1,   s[2*kt][3] * inv1);
                    pa[2] = pack2(s[2*kt+1][0] * inv0, s[2*kt+1][1] * inv0);
                    pa[3] = pack2(s[2*kt+1][2] * inv1, s[2*kt+1][3] * inv1);
                    #pragma unroll
                    for (int nt = 0; nt < 4; nt++)
                        MMA(o[nt], pa, vf[cur][nt]);
                }
            }
            // store O into O plane
            #pragma unroll
            for (int nt = 0; nt < 4; nt++) {
                int ch = (warp & 3) * 32 + nt * 8 + 2 * t4;
                int tok = (warp >> 2) * 32 + mf * 16 + g;
                *(uint32_t*)(smem + OHP + SWZ(tok, ch * 2)) = pack2(o[nt][0], o[nt][1]);
                *(uint32_t*)(smem + OHP + SWZ(tok + 8, ch * 2)) = pack2(o[nt][2], o[nt][3]);
            }
        }
    }
    __syncthreads();               // S4: O visible

    // ---- proj = O @ Wproj + bias; direct global scatter ----
    gemm(OHP, 3);
    {
        const float* bias = (const float*)(smem + BIASO);
        #pragma unroll
        for (int mf = 0; mf < 2; mf++) {
            const int tok0 = mbase + mf * 16 + g;
            const int tok1 = tok0 + 8;
            const int h0 = (hbase + (tok0 >> 3)) & 255, w0 = (wbase + (tok0 & 7)) & 255;
            const int h1 = (hbase + (tok1 >> 3)) & 255, w1 = (wbase + (tok1 & 7)) & 255;
            const size_t p0 = (size_t)h0 * 256 + w0;
            const size_t p1 = (size_t)h1 * 256 + w1;
            #pragma unroll
            for (int nt = 0; nt < 4; nt++) {
                const int c0 = nbase + nt * 8 + 2 * t4, c1 = c0 + 1;
                float* o0 = out + (size_t)(b * 128 + c0) * 65536;
                float* o1 = out + (size_t)(b * 128 + c1) * 65536;
                o0[p0] = acc[mf][nt][0] + bias[c0];
                o1[p0] = acc[mf][nt][1] + bias[c1];
                o0[p1] = acc[mf][nt][2] + bias[c0];
                o1[p1] = acc[mf][nt][3] + bias[c1];
            }
        }
    }
}

extern "C" void kernel_launch(void* const* d_in, const int* in_sizes, int n_in,
                              void* d_out, int out_size)
{
    const float* x      = (const float*)d_in[0];
    const float* w_qkv  = (const float*)d_in[1];
    const float* w_proj = (const float*)d_in[2];
    const float* b_proj = (const float*)d_in[3];
    float* out = (float*)d_out;

    prep_weights<<<128, 256>>>(w_qkv, w_proj);

    cudaFuncSetAttribute(swin_mma9_kernel,
                         cudaFuncAttributeMaxDynamicSharedMemorySize, SMEM_BYTES);
    swin_mma9_kernel<<<8192, 256, SMEM_BYTES>>>(x, b_proj, out);
}